// round 1
// baseline (speedup 1.0000x reference)
#include <cuda_runtime.h>
#include <math.h>

#define B_   8
#define L_   1024
#define H_   8
#define D_   64
#define HID  512
#define MTOT (B_ * L_)   // 8192

// Scratch (allocation-free rule: __device__ globals)
__device__ float g_q[B_ * H_ * L_ * D_];
__device__ float g_k[B_ * H_ * L_ * D_];
__device__ float g_v[B_ * H_ * L_ * D_];
__device__ float g_attn[MTOT * HID];

// ---------------------------------------------------------------------------
// QKV projection: Y = X @ W^T, fused RoPE epilogue for Q and K.
// Block tile 128(M) x 64(N), K-step 16. 256 threads as 16x16, thread 8x4.
// grid = (64, 24): blockIdx.y selects which of Wq/Wk/Wv and which head-column.
// ---------------------------------------------------------------------------
__global__ __launch_bounds__(256) void qkv_kernel(
    const float* __restrict__ x,
    const float* __restrict__ Wq,
    const float* __restrict__ Wk,
    const float* __restrict__ Wv)
{
    __shared__ float As[16][128];   // [k][m]
    __shared__ float Bs[16][64];    // [k][n]

    const int tid = threadIdx.x;
    const int tx = tid & 15, ty = tid >> 4;
    const int bm = blockIdx.x, bn = blockIdx.y;
    const int c0 = bn * 64;               // global output column base (0..1535)
    const int mat = c0 >> 9;              // 0=Q, 1=K, 2=V
    const float* W = (mat == 0) ? Wq : (mat == 1) ? Wk : Wv;
    float* dst = (mat == 0) ? g_q : (mat == 1) ? g_k : g_v;
    const int wrow0 = c0 & 511;           // row base inside the selected W
    const int m0 = bm * 128;

    float acc[8][4];
    #pragma unroll
    for (int i = 0; i < 8; i++)
        #pragma unroll
        for (int u = 0; u < 4; u++) acc[i][u] = 0.f;

    const int ra = tid >> 1, ka = (tid & 1) * 8;   // A loader: 128 rows x 16 k
    const int nb = tid >> 2, kb = (tid & 3) * 4;   // B loader: 64 rows  x 16 k

    for (int k0 = 0; k0 < HID; k0 += 16) {
        float4 a0 = *(const float4*)&x[(m0 + ra) * HID + k0 + ka];
        float4 a1 = *(const float4*)&x[(m0 + ra) * HID + k0 + ka + 4];
        float4 b0 = *(const float4*)&W[(wrow0 + nb) * HID + k0 + kb];
        As[ka + 0][ra] = a0.x; As[ka + 1][ra] = a0.y;
        As[ka + 2][ra] = a0.z; As[ka + 3][ra] = a0.w;
        As[ka + 4][ra] = a1.x; As[ka + 5][ra] = a1.y;
        As[ka + 6][ra] = a1.z; As[ka + 7][ra] = a1.w;
        Bs[kb + 0][nb] = b0.x; Bs[kb + 1][nb] = b0.y;
        Bs[kb + 2][nb] = b0.z; Bs[kb + 3][nb] = b0.w;
        __syncthreads();

        #pragma unroll
        for (int kk = 0; kk < 16; kk++) {
            float4 fa0 = *(float4*)&As[kk][ty * 8];
            float4 fa1 = *(float4*)&As[kk][ty * 8 + 4];
            float4 fb  = *(float4*)&Bs[kk][tx * 4];
            float a[8] = {fa0.x, fa0.y, fa0.z, fa0.w, fa1.x, fa1.y, fa1.z, fa1.w};
            float b[4] = {fb.x, fb.y, fb.z, fb.w};
            #pragma unroll
            for (int i = 0; i < 8; i++)
                #pragma unroll
                for (int u = 0; u < 4; u++)
                    acc[i][u] = fmaf(a[i], b[u], acc[i][u]);
        }
        __syncthreads();
    }

    // Epilogue: scatter into [B, H, L, D]; apply RoPE for Q and K.
    // Thread (ty,tx) owns rows m0+ty*8+i, local cols d = tx*4+u (one head: N-tile=64).
    // RoPE partner d^32 lives at tx^8 (8 lanes away, same warp) -> shfl_xor.
    const int h = (c0 >> 6) & 7;
    #pragma unroll
    for (int i = 0; i < 8; i++) {
        const int m = m0 + ty * 8 + i;
        const int b = m >> 10;
        const int l = m & 1023;
        #pragma unroll
        for (int u = 0; u < 4; u++) {
            const int d = tx * 4 + u;
            float val = acc[i][u];
            float partner = __shfl_xor_sync(0xffffffffu, val, 8);
            float outv;
            if (mat < 2) {
                const int i32 = d & 31;
                float inv = powf(10000.0f, -(float)i32 * (1.0f / 32.0f));
                float ang = (float)l * inv;
                float sn, cn;
                sincosf(ang, &sn, &cn);
                outv = (d < 32) ? (val * cn - partner * sn)
                                : (val * cn + partner * sn);
            } else {
                outv = val;
            }
            dst[((b * H_ + h) * L_ + l) * D_ + d] = outv;
        }
    }
}

// ---------------------------------------------------------------------------
// Flash attention, fp32. grid = (8 q-tiles, 8 heads, 8 batch), 256 threads.
// Q-tile 128 rows x 64 d; iterate 16 kv-tiles of 64 rows.
// Dynamic smem (96 KB): Qs[64][128] (d-major), Ks[64][64] (d-major),
//                       Vs[64][64] (row-major), Ps[128][64].
// Online softmax; row stats via 16-lane shfl_xor reductions.
// ---------------------------------------------------------------------------
extern __shared__ float attn_smem[];

__global__ __launch_bounds__(256) void attn_kernel()
{
    float* Qs = attn_smem;            // 64*128
    float* Ks = Qs + 64 * 128;        // 64*64
    float* Vs = Ks + 64 * 64;         // 64*64
    float* Ps = Vs + 64 * 64;         // 128*64

    const int tid = threadIdx.x;
    const int tx = tid & 15, ty = tid >> 4;
    const int q0 = blockIdx.x * 128;
    const int h = blockIdx.y, b = blockIdx.z;

    const float* gq  = g_q + ((b * H_ + h) * L_ + q0) * D_;
    const float* gkb = g_k + ((size_t)(b * H_ + h) * L_) * D_;
    const float* gvb = g_v + ((size_t)(b * H_ + h) * L_) * D_;

    // Load Q tile transposed: Qs[d][m]
    for (int idx = tid; idx < 2048; idx += 256) {
        const int row = idx >> 4;
        const int d0 = (idx & 15) * 4;
        float4 v = *(const float4*)&gq[row * D_ + d0];
        Qs[(d0 + 0) * 128 + row] = v.x;
        Qs[(d0 + 1) * 128 + row] = v.y;
        Qs[(d0 + 2) * 128 + row] = v.z;
        Qs[(d0 + 3) * 128 + row] = v.w;
    }

    float m_i[8], l_i[8], acc[8][4];
    #pragma unroll
    for (int i = 0; i < 8; i++) {
        m_i[i] = -1e30f; l_i[i] = 0.f;
        #pragma unroll
        for (int u = 0; u < 4; u++) acc[i][u] = 0.f;
    }

    for (int t = 0; t < 16; t++) {
        const int kv0 = t * 64;
        __syncthreads();   // previous Ps/Ks/Vs consumers done
        for (int idx = tid; idx < 1024; idx += 256) {
            const int j = idx >> 4;
            const int d0 = (idx & 15) * 4;
            float4 kv = *(const float4*)&gkb[(kv0 + j) * D_ + d0];
            Ks[(d0 + 0) * 64 + j] = kv.x;
            Ks[(d0 + 1) * 64 + j] = kv.y;
            Ks[(d0 + 2) * 64 + j] = kv.z;
            Ks[(d0 + 3) * 64 + j] = kv.w;
            ((float4*)Vs)[idx] = *(const float4*)&gvb[kv0 * D_ + idx * 4];
        }
        __syncthreads();

        // S = Q @ K^T * (1/8): thread tile 8 rows x 4 kv-cols
        float cs[8][4];
        #pragma unroll
        for (int i = 0; i < 8; i++)
            #pragma unroll
            for (int u = 0; u < 4; u++) cs[i][u] = 0.f;

        #pragma unroll 4
        for (int d = 0; d < 64; d++) {
            float4 fa0 = *(float4*)&Qs[d * 128 + ty * 8];
            float4 fa1 = *(float4*)&Qs[d * 128 + ty * 8 + 4];
            float4 fb  = *(float4*)&Ks[d * 64 + tx * 4];
            float a[8] = {fa0.x, fa0.y, fa0.z, fa0.w, fa1.x, fa1.y, fa1.z, fa1.w};
            float bb[4] = {fb.x, fb.y, fb.z, fb.w};
            #pragma unroll
            for (int i = 0; i < 8; i++)
                #pragma unroll
                for (int u = 0; u < 4; u++)
                    cs[i][u] = fmaf(a[i], bb[u], cs[i][u]);
        }

        // Online softmax update per row; 16-lane reductions across tx
        #pragma unroll
        for (int i = 0; i < 8; i++) {
            #pragma unroll
            for (int u = 0; u < 4; u++) cs[i][u] *= 0.125f;   // 1/sqrt(64)

            float mt = fmaxf(fmaxf(cs[i][0], cs[i][1]), fmaxf(cs[i][2], cs[i][3]));
            #pragma unroll
            for (int o = 1; o < 16; o <<= 1)
                mt = fmaxf(mt, __shfl_xor_sync(0xffffffffu, mt, o));

            const float mn = fmaxf(m_i[i], mt);
            const float alpha = __expf(m_i[i] - mn);
            m_i[i] = mn;

            float rs = 0.f;
            #pragma unroll
            for (int u = 0; u < 4; u++) {
                float p = __expf(cs[i][u] - mn);
                cs[i][u] = p;
                rs += p;
            }
            #pragma unroll
            for (int o = 1; o < 16; o <<= 1)
                rs += __shfl_xor_sync(0xffffffffu, rs, o);

            l_i[i] = l_i[i] * alpha + rs;
            #pragma unroll
            for (int u = 0; u < 4; u++) acc[i][u] *= alpha;

            *(float4*)&Ps[(ty * 8 + i) * 64 + tx * 4] =
                make_float4(cs[i][0], cs[i][1], cs[i][2], cs[i][3]);
        }
        __syncthreads();

        // acc += P @ V: thread tile 8 rows x 4 d-cols, contraction over j
        #pragma unroll 4
        for (int j = 0; j < 64; j++) {
            float4 fv = *(float4*)&Vs[j * 64 + tx * 4];
            float bb[4] = {fv.x, fv.y, fv.z, fv.w};
            #pragma unroll
            for (int i = 0; i < 8; i++) {
                float p = Ps[(ty * 8 + i) * 64 + j];
                #pragma unroll
                for (int u = 0; u < 4; u++)
                    acc[i][u] = fmaf(p, bb[u], acc[i][u]);
            }
        }
    }

    // Write out: [B, L, H*D] so the out-projection reads it contiguously
    #pragma unroll
    for (int i = 0; i < 8; i++) {
        const int row = q0 + ty * 8 + i;
        const float invl = 1.0f / l_i[i];
        #pragma unroll
        for (int u = 0; u < 4; u++) {
            g_attn[((size_t)(b * L_ + row)) * HID + h * D_ + tx * 4 + u] =
                acc[i][u] * invl;
        }
    }
}

// ---------------------------------------------------------------------------
// Output projection: out = g_attn @ Wo^T. Same tiling as qkv_kernel.
// grid = (64, 8)
// ---------------------------------------------------------------------------
__global__ __launch_bounds__(256) void outproj_kernel(
    const float* __restrict__ Wo, float* __restrict__ out)
{
    __shared__ float As[16][128];
    __shared__ float Bs[16][64];

    const int tid = threadIdx.x;
    const int tx = tid & 15, ty = tid >> 4;
    const int m0 = blockIdx.x * 128;
    const int c0 = blockIdx.y * 64;

    float acc[8][4];
    #pragma unroll
    for (int i = 0; i < 8; i++)
        #pragma unroll
        for (int u = 0; u < 4; u++) acc[i][u] = 0.f;

    const int ra = tid >> 1, ka = (tid & 1) * 8;
    const int nb = tid >> 2, kb = (tid & 3) * 4;

    for (int k0 = 0; k0 < HID; k0 += 16) {
        float4 a0 = *(const float4*)&g_attn[(size_t)(m0 + ra) * HID + k0 + ka];
        float4 a1 = *(const float4*)&g_attn[(size_t)(m0 + ra) * HID + k0 + ka + 4];
        float4 b0 = *(const float4*)&Wo[(c0 + nb) * HID + k0 + kb];
        As[ka + 0][ra] = a0.x; As[ka + 1][ra] = a0.y;
        As[ka + 2][ra] = a0.z; As[ka + 3][ra] = a0.w;
        As[ka + 4][ra] = a1.x; As[ka + 5][ra] = a1.y;
        As[ka + 6][ra] = a1.z; As[ka + 7][ra] = a1.w;
        Bs[kb + 0][nb] = b0.x; Bs[kb + 1][nb] = b0.y;
        Bs[kb + 2][nb] = b0.z; Bs[kb + 3][nb] = b0.w;
        __syncthreads();

        #pragma unroll
        for (int kk = 0; kk < 16; kk++) {
            float4 fa0 = *(float4*)&As[kk][ty * 8];
            float4 fa1 = *(float4*)&As[kk][ty * 8 + 4];
            float4 fb  = *(float4*)&Bs[kk][tx * 4];
            float a[8] = {fa0.x, fa0.y, fa0.z, fa0.w, fa1.x, fa1.y, fa1.z, fa1.w};
            float b[4] = {fb.x, fb.y, fb.z, fb.w};
            #pragma unroll
            for (int i = 0; i < 8; i++)
                #pragma unroll
                for (int u = 0; u < 4; u++)
                    acc[i][u] = fmaf(a[i], b[u], acc[i][u]);
        }
        __syncthreads();
    }

    #pragma unroll
    for (int i = 0; i < 8; i++) {
        const int m = m0 + ty * 8 + i;
        *(float4*)&out[(size_t)m * HID + c0 + tx * 4] =
            make_float4(acc[i][0], acc[i][1], acc[i][2], acc[i][3]);
    }
}

// ---------------------------------------------------------------------------
extern "C" void kernel_launch(void* const* d_in, const int* in_sizes, int n_in,
                              void* d_out, int out_size)
{
    const float* x  = (const float*)d_in[0];
    const float* Wq = (const float*)d_in[1];
    const float* Wk = (const float*)d_in[2];
    const float* Wv = (const float*)d_in[3];
    const float* Wo = (const float*)d_in[4];
    float* out = (float*)d_out;

    // >48KB dynamic smem opt-in (idempotent; not a stream op — capture-safe)
    cudaFuncSetAttribute(attn_kernel,
                         cudaFuncAttributeMaxDynamicSharedMemorySize, 98304);

    dim3 g1(64, 24);
    qkv_kernel<<<g1, 256>>>(x, Wq, Wk, Wv);

    dim3 g2(8, 8, 8);
    attn_kernel<<<g2, 256, 98304>>>();

    dim3 g3(64, 8);
    outproj_kernel<<<g3, 256>>>(Wo, out);
}

// round 2
// speedup vs baseline: 1.1491x; 1.1491x over previous
#include <cuda_runtime.h>
#include <math.h>

#define B_   8
#define L_   1024
#define H_   8
#define D_   64
#define HID  512
#define MTOT (B_ * L_)   // 8192

// Scratch (allocation-free rule: __device__ globals)
__device__ float g_q[B_ * H_ * L_ * D_];
__device__ float g_k[B_ * H_ * L_ * D_];
__device__ float g_v[B_ * H_ * L_ * D_];
__device__ float g_attn[MTOT * HID];

// ---------------------------------------------------------------------------
// QKV projection: Y = X @ W^T, fused RoPE epilogue for Q and K.
// Block tile 128(M) x 128(N) spanning 2 heads, K-step 16. 256 threads 16x16,
// thread tile 8x8 (cols split: tx*4 and 64+tx*4). Register gmem prefetch.
// grid = (64, 12): bn selects matrix (bn>>2) and 2-head column pair.
// ---------------------------------------------------------------------------
__global__ __launch_bounds__(256, 2) void qkv_kernel(
    const float* __restrict__ x,
    const float* __restrict__ Wq,
    const float* __restrict__ Wk,
    const float* __restrict__ Wv)
{
    __shared__ float As[16][128];   // [k][m]
    __shared__ float Bs[16][128];   // [k][n]

    const int tid = threadIdx.x;
    const int tx = tid & 15, ty = tid >> 4;
    const int m0 = blockIdx.x * 128;
    const int c0 = blockIdx.y * 128;
    const int mat = c0 >> 9;              // 0=Q, 1=K, 2=V
    const float* W = (mat == 0) ? Wq : (mat == 1) ? Wk : Wv;
    float* dst = (mat == 0) ? g_q : (mat == 1) ? g_k : g_v;
    const int wrow0 = c0 & 511;
    const int h0 = wrow0 >> 6;            // first of the two heads (0,2,4,6)

    // Loaders: each thread owns one row (of 128) and 8 consecutive k's.
    const int ra = tid >> 1, ka = (tid & 1) * 8;
    const float* ax = x + (size_t)(m0 + ra) * HID + ka;
    const float* bw = W + (size_t)(wrow0 + ra) * HID + ka;

    float4 pa0 = *(const float4*)(ax);
    float4 pa1 = *(const float4*)(ax + 4);
    float4 pb0 = *(const float4*)(bw);
    float4 pb1 = *(const float4*)(bw + 4);

    float acc[8][8];
    #pragma unroll
    for (int i = 0; i < 8; i++)
        #pragma unroll
        for (int u = 0; u < 8; u++) acc[i][u] = 0.f;

    for (int k0 = 0; k0 < HID; k0 += 16) {
        As[ka + 0][ra] = pa0.x; As[ka + 1][ra] = pa0.y;
        As[ka + 2][ra] = pa0.z; As[ka + 3][ra] = pa0.w;
        As[ka + 4][ra] = pa1.x; As[ka + 5][ra] = pa1.y;
        As[ka + 6][ra] = pa1.z; As[ka + 7][ra] = pa1.w;
        Bs[ka + 0][ra] = pb0.x; Bs[ka + 1][ra] = pb0.y;
        Bs[ka + 2][ra] = pb0.z; Bs[ka + 3][ra] = pb0.w;
        Bs[ka + 4][ra] = pb1.x; Bs[ka + 5][ra] = pb1.y;
        Bs[ka + 6][ra] = pb1.z; Bs[ka + 7][ra] = pb1.w;
        __syncthreads();

        if (k0 + 16 < HID) {
            pa0 = *(const float4*)(ax + k0 + 16);
            pa1 = *(const float4*)(ax + k0 + 20);
            pb0 = *(const float4*)(bw + k0 + 16);
            pb1 = *(const float4*)(bw + k0 + 20);
        }

        #pragma unroll
        for (int kk = 0; kk < 16; kk++) {
            float4 fa0 = *(float4*)&As[kk][ty * 8];
            float4 fa1 = *(float4*)&As[kk][ty * 8 + 4];
            float4 fb0 = *(float4*)&Bs[kk][tx * 4];
            float4 fb1 = *(float4*)&Bs[kk][64 + tx * 4];
            float a[8] = {fa0.x, fa0.y, fa0.z, fa0.w, fa1.x, fa1.y, fa1.z, fa1.w};
            float bb[8] = {fb0.x, fb0.y, fb0.z, fb0.w, fb1.x, fb1.y, fb1.z, fb1.w};
            #pragma unroll
            for (int i = 0; i < 8; i++)
                #pragma unroll
                for (int u = 0; u < 8; u++)
                    acc[i][u] = fmaf(a[i], bb[u], acc[i][u]);
        }
        __syncthreads();
    }

    // Epilogue: scatter into [B, H, L, D]; RoPE for Q/K.
    // d = tx*4+u for both column groups; partner d^32 is at lane tx^8.
    float freq[4];
    if (mat < 2) {
        #pragma unroll
        for (int u = 0; u < 4; u++) {
            const int i32 = (tx * 4 + u) & 31;
            freq[u] = __expf(-(float)i32 * 0.28782313662425572f); // ln(10000)/32
        }
    }

    #pragma unroll
    for (int i = 0; i < 8; i++) {
        const int m = m0 + ty * 8 + i;
        const int b = m >> 10;
        const int l = m & 1023;
        float* d0p = dst + ((size_t)(b * H_ + h0) * L_ + l) * D_;
        float* d1p = d0p + (size_t)L_ * D_;   // head h0+1
        if (mat < 2) {
            #pragma unroll
            for (int u = 0; u < 4; u++) {
                float sn, cn;
                sincosf((float)l * freq[u], &sn, &cn);
                const int d = tx * 4 + u;
                float v0 = acc[i][u];
                float v1 = acc[i][u + 4];
                float p0 = __shfl_xor_sync(0xffffffffu, v0, 8);
                float p1 = __shfl_xor_sync(0xffffffffu, v1, 8);
                float r0 = (d < 32) ? (v0 * cn - p0 * sn) : (v0 * cn + p0 * sn);
                float r1 = (d < 32) ? (v1 * cn - p1 * sn) : (v1 * cn + p1 * sn);
                d0p[d] = r0;
                d1p[d] = r1;
            }
        } else {
            *(float4*)&d0p[tx * 4] = make_float4(acc[i][0], acc[i][1], acc[i][2], acc[i][3]);
            *(float4*)&d1p[tx * 4] = make_float4(acc[i][4], acc[i][5], acc[i][6], acc[i][7]);
        }
    }
}

// ---------------------------------------------------------------------------
// Flash attention. grid = (8 q-tiles, 8 heads, 8 batch), 256 threads (16x16).
// Q-tile 128 x 64d; kv-tile 128. Q/K stored d-major with XOR swizzle
// (group ^ ((d>>2)&15)) so both transpose-store and compute-load are
// conflict-free. Smem 160KB: Qs[64][128], Ks[64][128], Vs[128][64], Ps[128][128].
// ---------------------------------------------------------------------------
extern __shared__ float attn_smem[];

__global__ __launch_bounds__(256, 1) void attn_kernel()
{
    float* Qs = attn_smem;            // 64*128 (swizzled, [d][m'])
    float* Ks = Qs + 64 * 128;        // 64*128 (swizzled, [d][j'])
    float* Vs = Ks + 64 * 128;        // 128*64 row-major
    float* Ps = Vs + 128 * 64;        // 128*128

    const int tid = threadIdx.x;
    const int tx = tid & 15, ty = tid >> 4;
    const int q0 = blockIdx.x * 128;
    const int h = blockIdx.y, b = blockIdx.z;

    const float* gq  = g_q + ((size_t)(b * H_ + h) * L_ + q0) * D_;
    const float* gkb = g_k + ((size_t)(b * H_ + h) * L_) * D_;
    const float* gvb = g_v + ((size_t)(b * H_ + h) * L_) * D_;

    // Load Q tile transposed+swizzled: logical (d, m) at col ((m>>2)^sg)*4+(m&3)
    for (int idx = tid; idx < 2048; idx += 256) {
        const int r = idx >> 4;              // m row
        const int d0 = (idx & 15) * 4;
        const int sg = idx & 15;             // (d>>2)&15 for these 4 d's
        float4 v = *(const float4*)&gq[r * D_ + d0];
        const int col = (((r >> 2) ^ sg) << 2) + (r & 3);
        Qs[(d0 + 0) * 128 + col] = v.x;
        Qs[(d0 + 1) * 128 + col] = v.y;
        Qs[(d0 + 2) * 128 + col] = v.z;
        Qs[(d0 + 3) * 128 + col] = v.w;
    }

    float m_i[8], l_i[8], acc[8][4];
    #pragma unroll
    for (int i = 0; i < 8; i++) {
        m_i[i] = -1e30f; l_i[i] = 0.f;
        #pragma unroll
        for (int u = 0; u < 4; u++) acc[i][u] = 0.f;
    }

    for (int t = 0; t < 8; t++) {
        const int kv0 = t * 128;
        __syncthreads();   // previous tile's consumers done
        for (int idx = tid; idx < 2048; idx += 256) {
            const int j = idx >> 4;
            const int d0 = (idx & 15) * 4;
            const int sg = idx & 15;
            float4 kv = *(const float4*)&gkb[(size_t)(kv0 + j) * D_ + d0];
            const int col = (((j >> 2) ^ sg) << 2) + (j & 3);
            Ks[(d0 + 0) * 128 + col] = kv.x;
            Ks[(d0 + 1) * 128 + col] = kv.y;
            Ks[(d0 + 2) * 128 + col] = kv.z;
            Ks[(d0 + 3) * 128 + col] = kv.w;
            ((float4*)Vs)[idx] = *(const float4*)&gvb[(size_t)kv0 * D_ + idx * 4];
        }
        __syncthreads();

        // S = Q @ K^T : thread tile 8 q-rows x 8 kv-cols (tx*4 and 64+tx*4)
        float cs[8][8];
        #pragma unroll
        for (int i = 0; i < 8; i++)
            #pragma unroll
            for (int u = 0; u < 8; u++) cs[i][u] = 0.f;

        #pragma unroll 8
        for (int d = 0; d < 64; d++) {
            const int sg = (d >> 2) & 15;
            float4 fa0 = *(float4*)&Qs[d * 128 + (((ty * 2) ^ sg) << 2)];
            float4 fa1 = *(float4*)&Qs[d * 128 + (((ty * 2 + 1) ^ sg) << 2)];
            float4 fb0 = *(float4*)&Ks[d * 128 + ((tx ^ sg) << 2)];
            float4 fb1 = *(float4*)&Ks[d * 128 + (((16 + tx) ^ sg) << 2)];
            float a[8] = {fa0.x, fa0.y, fa0.z, fa0.w, fa1.x, fa1.y, fa1.z, fa1.w};
            float bb[8] = {fb0.x, fb0.y, fb0.z, fb0.w, fb1.x, fb1.y, fb1.z, fb1.w};
            #pragma unroll
            for (int i = 0; i < 8; i++)
                #pragma unroll
                for (int u = 0; u < 8; u++)
                    cs[i][u] = fmaf(a[i], bb[u], cs[i][u]);
        }

        // Online softmax per row (16-lane shfl reductions across tx)
        #pragma unroll
        for (int i = 0; i < 8; i++) {
            #pragma unroll
            for (int u = 0; u < 8; u++) cs[i][u] *= 0.125f;   // 1/sqrt(64)

            float mt = cs[i][0];
            #pragma unroll
            for (int u = 1; u < 8; u++) mt = fmaxf(mt, cs[i][u]);
            #pragma unroll
            for (int o = 1; o < 16; o <<= 1)
                mt = fmaxf(mt, __shfl_xor_sync(0xffffffffu, mt, o));

            const float mn = fmaxf(m_i[i], mt);
            const float alpha = __expf(m_i[i] - mn);
            m_i[i] = mn;

            float rs = 0.f;
            #pragma unroll
            for (int u = 0; u < 8; u++) {
                float p = __expf(cs[i][u] - mn);
                cs[i][u] = p;
                rs += p;
            }
            #pragma unroll
            for (int o = 1; o < 16; o <<= 1)
                rs += __shfl_xor_sync(0xffffffffu, rs, o);

            l_i[i] = l_i[i] * alpha + rs;
            #pragma unroll
            for (int u = 0; u < 4; u++) acc[i][u] *= alpha;

            const int row = ty * 8 + i;
            *(float4*)&Ps[row * 128 + tx * 4] =
                make_float4(cs[i][0], cs[i][1], cs[i][2], cs[i][3]);
            *(float4*)&Ps[row * 128 + 64 + tx * 4] =
                make_float4(cs[i][4], cs[i][5], cs[i][6], cs[i][7]);
        }
        __syncthreads();

        // acc += P @ V : per 4-j chunk: 8 P-float4 (broadcast) + 4 V-float4
        #pragma unroll 2
        for (int j0 = 0; j0 < 128; j0 += 4) {
            float4 v0 = *(float4*)&Vs[(j0 + 0) * 64 + tx * 4];
            float4 v1 = *(float4*)&Vs[(j0 + 1) * 64 + tx * 4];
            float4 v2 = *(float4*)&Vs[(j0 + 2) * 64 + tx * 4];
            float4 v3 = *(float4*)&Vs[(j0 + 3) * 64 + tx * 4];
            #pragma unroll
            for (int i = 0; i < 8; i++) {
                float4 p = *(float4*)&Ps[(ty * 8 + i) * 128 + j0];
                acc[i][0] = fmaf(p.x, v0.x, acc[i][0]);
                acc[i][1] = fmaf(p.x, v0.y, acc[i][1]);
                acc[i][2] = fmaf(p.x, v0.z, acc[i][2]);
                acc[i][3] = fmaf(p.x, v0.w, acc[i][3]);
                acc[i][0] = fmaf(p.y, v1.x, acc[i][0]);
                acc[i][1] = fmaf(p.y, v1.y, acc[i][1]);
                acc[i][2] = fmaf(p.y, v1.z, acc[i][2]);
                acc[i][3] = fmaf(p.y, v1.w, acc[i][3]);
                acc[i][0] = fmaf(p.z, v2.x, acc[i][0]);
                acc[i][1] = fmaf(p.z, v2.y, acc[i][1]);
                acc[i][2] = fmaf(p.z, v2.z, acc[i][2]);
                acc[i][3] = fmaf(p.z, v2.w, acc[i][3]);
                acc[i][0] = fmaf(p.w, v3.x, acc[i][0]);
                acc[i][1] = fmaf(p.w, v3.y, acc[i][1]);
                acc[i][2] = fmaf(p.w, v3.z, acc[i][2]);
                acc[i][3] = fmaf(p.w, v3.w, acc[i][3]);
            }
        }
    }

    // Write out in [B, L, H*D] layout for the out-projection
    #pragma unroll
    for (int i = 0; i < 8; i++) {
        const int row = q0 + ty * 8 + i;
        const float invl = 1.0f / l_i[i];
        *(float4*)&g_attn[((size_t)(b * L_ + row)) * HID + h * D_ + tx * 4] =
            make_float4(acc[i][0] * invl, acc[i][1] * invl,
                        acc[i][2] * invl, acc[i][3] * invl);
    }
}

// ---------------------------------------------------------------------------
// Output projection: out = g_attn @ Wo^T. Same 128x128 tiling. grid = (64, 4)
// ---------------------------------------------------------------------------
__global__ __launch_bounds__(256, 2) void outproj_kernel(
    const float* __restrict__ Wo, float* __restrict__ out)
{
    __shared__ float As[16][128];
    __shared__ float Bs[16][128];

    const int tid = threadIdx.x;
    const int tx = tid & 15, ty = tid >> 4;
    const int m0 = blockIdx.x * 128;
    const int c0 = blockIdx.y * 128;

    const int ra = tid >> 1, ka = (tid & 1) * 8;
    const float* ax = g_attn + (size_t)(m0 + ra) * HID + ka;
    const float* bw = Wo + (size_t)(c0 + ra) * HID + ka;

    float4 pa0 = *(const float4*)(ax);
    float4 pa1 = *(const float4*)(ax + 4);
    float4 pb0 = *(const float4*)(bw);
    float4 pb1 = *(const float4*)(bw + 4);

    float acc[8][8];
    #pragma unroll
    for (int i = 0; i < 8; i++)
        #pragma unroll
        for (int u = 0; u < 8; u++) acc[i][u] = 0.f;

    for (int k0 = 0; k0 < HID; k0 += 16) {
        As[ka + 0][ra] = pa0.x; As[ka + 1][ra] = pa0.y;
        As[ka + 2][ra] = pa0.z; As[ka + 3][ra] = pa0.w;
        As[ka + 4][ra] = pa1.x; As[ka + 5][ra] = pa1.y;
        As[ka + 6][ra] = pa1.z; As[ka + 7][ra] = pa1.w;
        Bs[ka + 0][ra] = pb0.x; Bs[ka + 1][ra] = pb0.y;
        Bs[ka + 2][ra] = pb0.z; Bs[ka + 3][ra] = pb0.w;
        Bs[ka + 4][ra] = pb1.x; Bs[ka + 5][ra] = pb1.y;
        Bs[ka + 6][ra] = pb1.z; Bs[ka + 7][ra] = pb1.w;
        __syncthreads();

        if (k0 + 16 < HID) {
            pa0 = *(const float4*)(ax + k0 + 16);
            pa1 = *(const float4*)(ax + k0 + 20);
            pb0 = *(const float4*)(bw + k0 + 16);
            pb1 = *(const float4*)(bw + k0 + 20);
        }

        #pragma unroll
        for (int kk = 0; kk < 16; kk++) {
            float4 fa0 = *(float4*)&As[kk][ty * 8];
            float4 fa1 = *(float4*)&As[kk][ty * 8 + 4];
            float4 fb0 = *(float4*)&Bs[kk][tx * 4];
            float4 fb1 = *(float4*)&Bs[kk][64 + tx * 4];
            float a[8] = {fa0.x, fa0.y, fa0.z, fa0.w, fa1.x, fa1.y, fa1.z, fa1.w};
            float bb[8] = {fb0.x, fb0.y, fb0.z, fb0.w, fb1.x, fb1.y, fb1.z, fb1.w};
            #pragma unroll
            for (int i = 0; i < 8; i++)
                #pragma unroll
                for (int u = 0; u < 8; u++)
                    acc[i][u] = fmaf(a[i], bb[u], acc[i][u]);
        }
        __syncthreads();
    }

    #pragma unroll
    for (int i = 0; i < 8; i++) {
        const int m = m0 + ty * 8 + i;
        *(float4*)&out[(size_t)m * HID + c0 + tx * 4] =
            make_float4(acc[i][0], acc[i][1], acc[i][2], acc[i][3]);
        *(float4*)&out[(size_t)m * HID + c0 + 64 + tx * 4] =
            make_float4(acc[i][4], acc[i][5], acc[i][6], acc[i][7]);
    }
}

// ---------------------------------------------------------------------------
extern "C" void kernel_launch(void* const* d_in, const int* in_sizes, int n_in,
                              void* d_out, int out_size)
{
    const float* x  = (const float*)d_in[0];
    const float* Wq = (const float*)d_in[1];
    const float* Wk = (const float*)d_in[2];
    const float* Wv = (const float*)d_in[3];
    const float* Wo = (const float*)d_in[4];
    float* out = (float*)d_out;

    cudaFuncSetAttribute(attn_kernel,
                         cudaFuncAttributeMaxDynamicSharedMemorySize, 163840);

    dim3 g1(64, 12);
    qkv_kernel<<<g1, 256>>>(x, Wq, Wk, Wv);

    dim3 g2(8, 8, 8);
    attn_kernel<<<g2, 256, 163840>>>();

    dim3 g3(64, 4);
    outproj_kernel<<<g3, 256>>>(Wo, out);
}